// round 5
// baseline (speedup 1.0000x reference)
#include <cuda_runtime.h>
#include <math.h>
#include <stdint.h>

#define BB    64
#define TT    2048
#define ENCD  512
#define DECD  1024
#define CONVC 32
#define KW    31
#define HID   256
#define PADW  15

// Packed f32x2 FMA (sm_100+; SASS FFMA2 — reachable only via PTX)
#define FMA_F32X2(d, a, b, c) \
    asm("fma.rn.f32x2 %0, %1, %2, %3;" : "=l"(d) : "l"(a), "l"(b), "l"(c))
#define PACK_F32X2(out, lo, hi) \
    asm("mov.b64 %0, {%1, %2};" : "=l"(out) : "f"(lo), "f"(hi))
#define UNPACK_F32X2(lo, hi, in) \
    asm("mov.b64 {%0, %1}, %2;" : "=f"(lo), "=f"(hi) : "l"(in))

// ---------------- device scratch (no allocations allowed) ----------------
__device__ float g_Wt[ENCD * HID];   // W_enc transposed: [e][h]
__device__ float g_Mt[KW * HID];     // (W_att @ conv_w) transposed: [k][h]
__device__ float g_dec[BB * HID];    // dec_state @ W_dec^T
__device__ float g_energy[BB * TT];  // pre-softmax energies (masked)

// ---------------- tiny prep kernels ----------------
__global__ void k_transpose(const float* __restrict__ W_enc) {
    int idx = blockIdx.x * 256 + threadIdx.x;      // over ENCD*HID
    int e = idx / HID;
    int h = idx - e * HID;
    g_Wt[idx] = W_enc[h * ENCD + e];
}

__global__ void k_M(const float* __restrict__ W_att, const float* __restrict__ conv_w) {
    int h = threadIdx.x;                           // 256 threads
    for (int k = 0; k < KW; k++) {
        float s = 0.f;
        for (int c = 0; c < CONVC; c++)
            s += W_att[h * CONVC + c] * conv_w[c * KW + k];
        g_Mt[k * HID + h] = s;
    }
}

__global__ void k_dec(const float* __restrict__ W_dec, const float* __restrict__ dec_state) {
    int b = blockIdx.x;
    int h = threadIdx.x;
    const float4* w4 = (const float4*)(W_dec + h * DECD);
    const float4* d4 = (const float4*)(dec_state + b * DECD);
    float s = 0.f;
    for (int i = 0; i < DECD / 4; i++) {
        float4 w = w4[i];
        float4 d = d4[i];
        s += w.x * d.x + w.y * d.y + w.z * d.z + w.w * d.w;
    }
    g_dec[b * HID + h] = s;
}

// ---------------- fused energy kernel ----------------
// Block: 256 threads, tile = 64 t x 256 h. K loop: 32 chunks of 16 over ENC,
// plus 2 tail chunks implementing the location-conv term as extra GEMM K-steps:
//   loc(t,h) = sum_k Mt[k][h] * prev[b, t0+t-15+k]
// Inner product uses packed f32x2 FMAs (j-dimension pairs); fp32-exact.
// Epilogue: energy = w_b + sum_h w_w[h]*tanh(acc + dec[b,h] + b_enc[h]), mask, store.
__global__ __launch_bounds__(256, 2)
void k_energy(const float* __restrict__ enc, const float* __restrict__ prev,
              const int* __restrict__ text_len, const float* __restrict__ b_enc,
              const float* __restrict__ w_w, const float* __restrict__ w_b) {
    __shared__ float As[16][68];        // [k][t], padded
    __shared__ float Ws[16][256];       // [k][h]
    __shared__ float s_prev[96];        // prev window [t0-15, t0+79]
    __shared__ float s_dec[HID], s_benc[HID], s_ww[HID];

    const int b   = blockIdx.y;
    const int t0  = blockIdx.x * 64;
    const int tid = threadIdx.x;
    const int tcol = tid & 31;          // -> h block: tcol*8 .. +8
    const int trow = tid >> 5;          // -> t block: trow*8 .. +8  (one warp per trow)

    if (tid < 96) {
        int idx = t0 - PADW + tid;
        s_prev[tid] = (tid < 95 && idx >= 0 && idx < TT) ? prev[b * TT + idx] : 0.f;
    }
    s_dec[tid]  = g_dec[b * HID + tid];
    s_benc[tid] = b_enc[tid];
    s_ww[tid]   = w_w[tid];

    // acc2[i][j2]: packed pair = (acc[i][2*j2], acc[i][2*j2+1])
    uint64_t acc2[8][4];
#pragma unroll
    for (int i = 0; i < 8; i++)
#pragma unroll
        for (int j = 0; j < 4; j++) acc2[i][j] = 0ull;

    const float* encB = enc + ((size_t)b * TT + t0) * ENCD;

    const int a_row = tid >> 2;         // 0..63
    const int a_q   = tid & 3;          // 0..3 (float4 within 16)

    for (int c = 0; c < 34; c++) {
        __syncthreads();
        if (c < 32) {
            const int k0 = c * 16;
            // Ws: 16x256 = 1024 float4, 4 per thread (coalesced from g_Wt)
#pragma unroll
            for (int j = 0; j < 4; j++) {
                int lin = tid + j * 256;          // 0..1023
                int r   = lin >> 6;               // 0..15
                int c4  = lin & 63;               // float4 col
                float4 v = *(const float4*)(g_Wt + (size_t)(k0 + r) * HID + c4 * 4);
                *(float4*)(&Ws[r][c4 * 4]) = v;
            }
            // As: 64x16 = 256 float4, 1 per thread; store transposed [k][t]
            float4 v = *(const float4*)(encB + (size_t)a_row * ENCD + k0 + a_q * 4);
            As[a_q * 4 + 0][a_row] = v.x;
            As[a_q * 4 + 1][a_row] = v.y;
            As[a_q * 4 + 2][a_row] = v.z;
            As[a_q * 4 + 3][a_row] = v.w;
        } else {
            const int kb = (c - 32) * 16;         // 0 or 16
#pragma unroll
            for (int j = 0; j < 4; j++) {
                int lin = tid + j * 256;
                int r   = lin >> 6;
                int c4  = lin & 63;
                int kg  = kb + r;
                float4 v = make_float4(0.f, 0.f, 0.f, 0.f);
                if (kg < KW) v = *(const float4*)(g_Mt + (size_t)kg * HID + c4 * 4);
                *(float4*)(&Ws[r][c4 * 4]) = v;
            }
#pragma unroll
            for (int i = 0; i < 4; i++) {
                int k = a_q * 4 + i;
                As[k][a_row] = s_prev[a_row + kb + k];  // max index 63+31=94 < 96
            }
        }
        __syncthreads();

#pragma unroll
        for (int k = 0; k < 16; k++) {
            float4 a0 = *(const float4*)(&As[k][trow * 8]);
            float4 a1 = *(const float4*)(&As[k][trow * 8 + 4]);
            // w pairs: 4x aligned 64-bit loads (pairs along h)
            const uint64_t* wp = (const uint64_t*)(&Ws[k][tcol * 8]);
            uint64_t w2[4];
            w2[0] = wp[0]; w2[1] = wp[1]; w2[2] = wp[2]; w2[3] = wp[3];
            float a[8] = {a0.x, a0.y, a0.z, a0.w, a1.x, a1.y, a1.z, a1.w};
#pragma unroll
            for (int i = 0; i < 8; i++) {
                uint64_t a2;
                PACK_F32X2(a2, a[i], a[i]);
#pragma unroll
                for (int j = 0; j < 4; j++)
                    FMA_F32X2(acc2[i][j], a2, w2[j], acc2[i][j]);
            }
        }
    }

    // unpack accumulators
    float acc[8][8];
#pragma unroll
    for (int i = 0; i < 8; i++)
#pragma unroll
        for (int j = 0; j < 4; j++)
            UNPACK_F32X2(acc[i][2 * j], acc[i][2 * j + 1], acc2[i][j]);

    // epilogue
    float dw8[8], ww8[8];
#pragma unroll
    for (int j = 0; j < 8; j++) {
        int h = tcol * 8 + j;
        dw8[j] = s_dec[h] + s_benc[h];
        ww8[j] = s_ww[h];
    }
    const int tl = text_len[b];
    const float wb = w_b[0];
    const float NEG_INF = __int_as_float(0xff800000u);

#pragma unroll
    for (int i = 0; i < 8; i++) {
        float e = 0.f;
#pragma unroll
        for (int j = 0; j < 8; j++)
            e += ww8[j] * tanhf(acc[i][j] + dw8[j]);
#pragma unroll
        for (int off = 16; off > 0; off >>= 1)
            e += __shfl_down_sync(0xffffffffu, e, off);
        if (tcol == 0) {
            int t = t0 + trow * 8 + i;
            g_energy[b * TT + t] = (t >= tl) ? NEG_INF : (e + wb);
        }
    }
}

// ---------------- softmax over T per batch ----------------
__global__ void k_softmax(float* __restrict__ attw_out) {
    __shared__ float red[256];
    const int b = blockIdx.x, tid = threadIdx.x;
    float v[8];
    float m = __int_as_float(0xff800000u);
#pragma unroll
    for (int i = 0; i < 8; i++) {
        v[i] = g_energy[b * TT + tid + i * 256];
        m = fmaxf(m, v[i]);
    }
    red[tid] = m;
    __syncthreads();
    for (int s = 128; s > 0; s >>= 1) {
        if (tid < s) red[tid] = fmaxf(red[tid], red[tid + s]);
        __syncthreads();
    }
    const float mx = red[0];
    __syncthreads();
    float sum = 0.f;
#pragma unroll
    for (int i = 0; i < 8; i++) {
        v[i] = expf(v[i] - mx);    // exp(-inf)=0 for masked
        sum += v[i];
    }
    red[tid] = sum;
    __syncthreads();
    for (int s = 128; s > 0; s >>= 1) {
        if (tid < s) red[tid] += red[tid + s];
        __syncthreads();
    }
    const float inv = 1.f / red[0];
#pragma unroll
    for (int i = 0; i < 8; i++)
        attw_out[b * TT + tid + i * 256] = v[i] * inv;
}

// ---------------- context vector: att_c[b][e] = sum_t attw[b][t]*enc[b][t][e] ----------------
__global__ __launch_bounds__(256)
void k_attc(const float* __restrict__ enc, const float* __restrict__ attw,
            float* __restrict__ out) {
    __shared__ float sw[TT];
    const int b = blockIdx.y, tid = threadIdx.x;
    const int e = blockIdx.x * 256 + tid;
#pragma unroll
    for (int i = 0; i < 8; i++)
        sw[tid + i * 256] = attw[b * TT + tid + i * 256];
    __syncthreads();

    const float* ep = enc + (size_t)b * TT * ENCD + e;
    float a0 = 0.f, a1 = 0.f, a2 = 0.f, a3 = 0.f;
    float a4 = 0.f, a5 = 0.f, a6 = 0.f, a7 = 0.f;
    for (int t = 0; t < TT; t += 8) {
        a0 = fmaf(sw[t + 0], ep[(size_t)(t + 0) * ENCD], a0);
        a1 = fmaf(sw[t + 1], ep[(size_t)(t + 1) * ENCD], a1);
        a2 = fmaf(sw[t + 2], ep[(size_t)(t + 2) * ENCD], a2);
        a3 = fmaf(sw[t + 3], ep[(size_t)(t + 3) * ENCD], a3);
        a4 = fmaf(sw[t + 4], ep[(size_t)(t + 4) * ENCD], a4);
        a5 = fmaf(sw[t + 5], ep[(size_t)(t + 5) * ENCD], a5);
        a6 = fmaf(sw[t + 6], ep[(size_t)(t + 6) * ENCD], a6);
        a7 = fmaf(sw[t + 7], ep[(size_t)(t + 7) * ENCD], a7);
    }
    out[b * ENCD + e] = ((a0 + a1) + (a2 + a3)) + ((a4 + a5) + (a6 + a7));
}

// ---------------- launch ----------------
extern "C" void kernel_launch(void* const* d_in, const int* in_sizes, int n_in,
                              void* d_out, int out_size) {
    const float* enc       = (const float*)d_in[0];
    const float* dec_state = (const float*)d_in[1];
    const float* prev      = (const float*)d_in[2];
    const int*   text_len  = (const int*)  d_in[3];
    const float* W_enc     = (const float*)d_in[4];
    const float* b_enc     = (const float*)d_in[5];
    const float* W_dec     = (const float*)d_in[6];
    const float* W_att     = (const float*)d_in[7];
    const float* conv_w    = (const float*)d_in[8];
    const float* w_w       = (const float*)d_in[9];
    const float* w_b       = (const float*)d_in[10];

    float* out      = (float*)d_out;          // att_c: [B, ENC]
    float* out_attw = out + BB * ENCD;        // att_w: [B, T]

    k_transpose<<<(ENCD * HID) / 256, 256>>>(W_enc);
    k_M<<<1, 256>>>(W_att, conv_w);
    k_dec<<<BB, 256>>>(W_dec, dec_state);
    k_energy<<<dim3(TT / 64, BB), 256>>>(enc, prev, text_len, b_enc, w_w, w_b);
    k_softmax<<<BB, 256>>>(out_attw);
    k_attc<<<dim3(ENCD / 256, BB), 256>>>(enc, out_attw, out);
}